// round 3
// baseline (speedup 1.0000x reference)
#include <cuda_runtime.h>

#define NB 2
#define NSEQ 2304
#define NH 8
#define HD 32
#define DIMC 256
#define NTAB 9025
#define CPBH 512
#define MROWS (NB*NSEQ)          // 4608
#define NROWS (NB*NH*NSEQ)       // 36864

typedef unsigned long long u64;

// ---- packed f32x2 helpers (Blackwell FFMA2 — PTX only) ----
__device__ __forceinline__ u64 pk(float lo, float hi) {
    u64 r; asm("mov.b64 %0,{%1,%2};" : "=l"(r) : "f"(lo), "f"(hi)); return r;
}
__device__ __forceinline__ void upk(u64 v, float& lo, float& hi) {
    asm("mov.b64 {%0,%1},%2;" : "=f"(lo), "=f"(hi) : "l"(v));
}
__device__ __forceinline__ u64 f2fma(u64 a, u64 b, u64 c) {
    u64 r; asm("fma.rn.f32x2 %0,%1,%2,%3;" : "=l"(r) : "l"(a), "l"(b), "l"(c)); return r;
}
__device__ __forceinline__ u64 f2add(u64 a, u64 b) {
    u64 r; asm("add.rn.f32x2 %0,%1,%2;" : "=l"(r) : "l"(a), "l"(b)); return r;
}

// -------- device scratch --------
__device__ float g_qkv[MROWS*3*DIMC];
__device__ float g_q[NROWS*HD];
__device__ float g_k[NROWS*HD];
__device__ float g_v[NROWS*HD];
__device__ float g_att[MROWS*DIMC];
__device__ float g_tab[NH*NTAB];
__device__ int   g_idxT[NSEQ*NSEQ];         // TRANSPOSED: [m][n]
__device__ float g_qnm[NROWS];              // ||qn|| per row
__device__ float g_maxb[NH];                // max bias per head
__device__ float g_pacc[2][NROWS*HD];       // split-K partial numerators
__device__ float g_pl[2][NROWS];            // split-K partial denominators
__device__ int   g_is64;

// -------- dtype probe --------
__global__ void k_flag_init() { g_is64 = 1; }

__global__ void k_flag_scan(const long long* __restrict__ p) {
    // scan 2M int64 slots (safe whichever dtype the buffer really is)
    const long total = 2000000;
    for (long i = (long)blockIdx.x * blockDim.x + threadIdx.x; i < total;
         i += (long)gridDim.x * blockDim.x) {
        long long v = p[i];
        if (v < 0 || v >= NTAB) g_is64 = 0;
    }
}

// -------- convert int64->int32 AND transpose (tiled) --------
__global__ void k_idx_convert(const long long* __restrict__ p) {
    __shared__ int t[32][33];
    int is64 = g_is64;
    const int* p32 = (const int*)p;
    int bx = blockIdx.x * 32, by = blockIdx.y * 32;
    #pragma unroll
    for (int j = 0; j < 32; j += 8) {
        long src = (long)(by + threadIdx.y + j) * NSEQ + bx + threadIdx.x;
        t[threadIdx.y + j][threadIdx.x] = is64 ? (int)p[src] : p32[src];
    }
    __syncthreads();
    #pragma unroll
    for (int j = 0; j < 32; j += 8) {
        long dst = (long)(bx + threadIdx.y + j) * NSEQ + by + threadIdx.x;
        g_idxT[dst] = t[threadIdx.x][threadIdx.y + j];
    }
}

// -------- CPB MLP: weights staged in SMEM, 1 thread per table row --------
__global__ void __launch_bounds__(256) k_cpb(
        const float* __restrict__ tbl, const float* __restrict__ W1,
        const float* __restrict__ b1, const float* __restrict__ W2,
        const float* __restrict__ b2) {
    __shared__ float W1s[2*CPBH];
    __shared__ float b1s[CPBH];
    __shared__ __align__(8) float W2T[CPBH*NH];     // [j][h]
    int tid = threadIdx.x;
    for (int i = tid; i < 2*CPBH; i += 256) W1s[i] = W1[i];
    for (int i = tid; i < CPBH;   i += 256) b1s[i] = b1[i];
    for (int i = tid; i < NH*CPBH; i += 256) {
        int hh = i >> 9, j = i & (CPBH-1);
        W2T[j*NH + hh] = W2[i];
    }
    __syncthreads();
    int w = blockIdx.x * 256 + tid;
    if (w >= NTAB) return;
    float c0 = tbl[2*w], c1 = tbl[2*w+1];
    u64 acc[4] = {0ull, 0ull, 0ull, 0ull};
    #pragma unroll 4
    for (int j = 0; j < CPBH; j++) {
        float hd = fmaxf(fmaf(c0, W1s[2*j], fmaf(c1, W1s[2*j+1], b1s[j])), 0.f);
        u64 hh = pk(hd, hd);
        const u64* wp = (const u64*)(W2T + j*NH);
        acc[0] = f2fma(hh, wp[0], acc[0]);
        acc[1] = f2fma(hh, wp[1], acc[1]);
        acc[2] = f2fma(hh, wp[2], acc[2]);
        acc[3] = f2fma(hh, wp[3], acc[3]);
    }
    #pragma unroll
    for (int i = 0; i < 4; i++) {
        float lo, hi; upk(acc[i], lo, hi);
        g_tab[(2*i  )*NTAB + w] = lo + b2[2*i];
        g_tab[(2*i+1)*NTAB + w] = hi + b2[2*i+1];
    }
}

// -------- per-head max bias --------
__global__ void k_maxb() {
    int h = threadIdx.y, lane = threadIdx.x;
    float m = -1e30f;
    for (int i = lane; i < NTAB; i += 32) m = fmaxf(m, g_tab[h*NTAB + i]);
    #pragma unroll
    for (int off = 16; off; off >>= 1)
        m = fmaxf(m, __shfl_xor_sync(0xffffffffu, m, off));
    if (lane == 0) g_maxb[h] = m;
}

// -------- tiled fp32 GEMM with packed FFMA2: C = A @ W^T + bias --------
#define BM 128
#define BN 64
#define BK 16
__global__ void __launch_bounds__(256) k_gemm(
        const float* __restrict__ A, const float* __restrict__ W,
        const float* __restrict__ bias, float* __restrict__ C,
        int M, int N, int K) {
    __shared__ __align__(16) float As[BK][BM];
    __shared__ __align__(16) float Bs[BK][BN];
    int tid = threadIdx.x;
    int row0 = blockIdx.y * BM, col0 = blockIdx.x * BN;
    int ty = tid >> 4, tx = tid & 15;
    u64 acc2[4][4];
    #pragma unroll
    for (int i = 0; i < 4; i++)
        #pragma unroll
        for (int j = 0; j < 4; j++) acc2[i][j] = 0ull;

    for (int k0 = 0; k0 < K; k0 += BK) {
        #pragma unroll
        for (int jj = 0; jj < 2; jj++) {
            int f = tid + jj * 256;
            int ar = f >> 2, ac = (f & 3) << 2;
            float4 v = *(const float4*)(A + (size_t)(row0 + ar) * K + k0 + ac);
            As[ac  ][ar] = v.x; As[ac+1][ar] = v.y;
            As[ac+2][ar] = v.z; As[ac+3][ar] = v.w;
        }
        {
            int f = tid;
            int br = f >> 2, bc = (f & 3) << 2;
            float4 v = *(const float4*)(W + (size_t)(col0 + br) * K + k0 + bc);
            Bs[bc  ][br] = v.x; Bs[bc+1][br] = v.y;
            Bs[bc+2][br] = v.z; Bs[bc+3][br] = v.w;
        }
        __syncthreads();
        #pragma unroll
        for (int kk = 0; kk < BK; kk++) {
            ulonglong2 aA = *(const ulonglong2*)&As[kk][ty*8];
            ulonglong2 aB = *(const ulonglong2*)&As[kk][ty*8 + 4];
            u64 a2[4] = {aA.x, aA.y, aB.x, aB.y};
            float4 bq = *(const float4*)&Bs[kk][tx*4];
            u64 bd[4] = {pk(bq.x,bq.x), pk(bq.y,bq.y), pk(bq.z,bq.z), pk(bq.w,bq.w)};
            #pragma unroll
            for (int i = 0; i < 4; i++)
                #pragma unroll
                for (int j = 0; j < 4; j++)
                    acc2[i][j] = f2fma(a2[i], bd[j], acc2[i][j]);
        }
        __syncthreads();
    }
    float4 bb = *(const float4*)(bias + col0 + tx*4);
    #pragma unroll
    for (int i = 0; i < 4; i++) {
        float lo[4], hi[4];
        #pragma unroll
        for (int j = 0; j < 4; j++) upk(acc2[i][j], lo[j], hi[j]);
        float4 o0, o1;
        o0.x = lo[0]+bb.x; o0.y = lo[1]+bb.y; o0.z = lo[2]+bb.z; o0.w = lo[3]+bb.w;
        o1.x = hi[0]+bb.x; o1.y = hi[1]+bb.y; o1.z = hi[2]+bb.z; o1.w = hi[3]+bb.w;
        *(float4*)(C + (size_t)(row0 + ty*8 + 2*i    ) * N + col0 + tx*4) = o0;
        *(float4*)(C + (size_t)(row0 + ty*8 + 2*i + 1) * N + col0 + tx*4) = o1;
    }
}

// -------- qkv postprocess: split, normalize, scale; also store ||qn|| --------
__global__ void k_qkvpost(const float* __restrict__ temp, const float* __restrict__ seq,
                          const float* __restrict__ emb) {
    int gid = blockIdx.x * 4 + (threadIdx.x >> 5);
    int lane = threadIdx.x & 31;
    int n  = gid % NSEQ;
    int bh = gid / NSEQ;
    int h = bh & 7, b = bh >> 3;
    const float* rp = g_qkv + (size_t)(b * NSEQ + n) * (3 * DIMC);
    float qv = rp[            h * HD + lane];
    float kv = rp[DIMC      + h * HD + lane];
    float vv = rp[2 * DIMC  + h * HD + lane];
    float sq = qv * qv, sk = kv * kv;
    #pragma unroll
    for (int off = 16; off; off >>= 1) {
        sq += __shfl_xor_sync(0xffffffffu, sq, off);
        sk += __shfl_xor_sync(0xffffffffu, sk, off);
    }
    sq = sqrtf(sq); sk = sqrtf(sk);
    float scale = log1pf(expf(temp[h])) * seq[0];
    float qn = (qv / fmaxf(sq, 1e-12f) + emb[h * HD + lane]) * scale;
    float kn =  kv / fmaxf(sk, 1e-12f);
    size_t o = (size_t)gid * HD + lane;
    g_q[o] = qn; g_k[o] = kn; g_v[o] = vv;
    float s2 = qn * qn;
    #pragma unroll
    for (int off = 16; off; off >>= 1)
        s2 += __shfl_xor_sync(0xffffffffu, s2, off);
    if (lane == 0) g_qnm[gid] = sqrtf(s2);
}

// -------- flash attention, fixed-max softmax, split-K x2 --------
#define FT 256
#define MTILE 32
#define KSPLIT (NSEQ/2)                               // 1152
#define TAB_PAD 9056
__global__ void __launch_bounds__(FT) k_flash() {
    extern __shared__ __align__(16) float dsm[];
    float* tab_s = dsm;                               // 9056 floats
    float* Ks    = dsm + TAB_PAD;                     // 1024 floats
    float* Vs    = dsm + TAB_PAD + 1024;              // 1024 floats
    int*   idx_s = (int*)(dsm + TAB_PAD + 2048);      // 32*256 ints

    int tid = threadIdx.x;
    int bh = blockIdx.x;
    int h = bh & 7;
    int n = blockIdx.y * FT + tid;
    int kt = blockIdx.z;

    for (int i = tid; i < NTAB; i += FT) tab_s[i] = g_tab[h * NTAB + i];

    int row = bh * NSEQ + n;
    float mx = g_qnm[row] + g_maxb[h];

    u64 q2[16];
    const ulonglong2* qp = (const ulonglong2*)(g_q + (size_t)row * HD);
    #pragma unroll
    for (int i = 0; i < 8; i++) { ulonglong2 t = qp[i]; q2[2*i] = t.x; q2[2*i+1] = t.y; }

    u64 acc2[16];
    #pragma unroll
    for (int i = 0; i < 16; i++) acc2[i] = 0ull;
    float l = 0.f;

    const float* kb = g_k + ((size_t)bh * NSEQ + kt * KSPLIT) * HD;
    const float* vb = g_v + ((size_t)bh * NSEQ + kt * KSPLIT) * HD;
    const int*   ib = g_idxT + (size_t)(kt * KSPLIT) * NSEQ;

    for (int m0 = 0; m0 < KSPLIT; m0 += MTILE) {
        __syncthreads();                               // covers tab_s on iter 0
        ((float4*)Ks)[tid] = *(const float4*)(kb + (size_t)m0 * HD + tid * 4);
        ((float4*)Vs)[tid] = *(const float4*)(vb + (size_t)m0 * HD + tid * 4);
        #pragma unroll
        for (int m = 0; m < MTILE; m++)
            idx_s[m * FT + tid] = ib[(size_t)(m0 + m) * NSEQ + n];
        __syncthreads();
        #pragma unroll 2
        for (int m = 0; m < MTILE; m++) {
            float bias = tab_s[idx_s[m * FT + tid]];
            const ulonglong2* kr = (const ulonglong2*)(Ks + m * HD);
            u64 s0 = pk(bias, 0.f), s1 = 0ull, s2 = 0ull, s3 = 0ull;
            #pragma unroll
            for (int i = 0; i < 4; i++) {
                ulonglong2 ka = kr[2*i], kbb = kr[2*i+1];
                s0 = f2fma(q2[4*i  ], ka.x,  s0);
                s1 = f2fma(q2[4*i+1], ka.y,  s1);
                s2 = f2fma(q2[4*i+2], kbb.x, s2);
                s3 = f2fma(q2[4*i+3], kbb.y, s3);
            }
            u64 st = f2add(f2add(s0, s1), f2add(s2, s3));
            float slo, shi; upk(st, slo, shi);
            float p = __expf(slo + shi - mx);          // fixed max: no branch, no rescale
            l += p;
            u64 pp = pk(p, p);
            const ulonglong2* vr = (const ulonglong2*)(Vs + m * HD);
            #pragma unroll
            for (int i = 0; i < 8; i++) {
                ulonglong2 vv = vr[i];
                acc2[2*i  ] = f2fma(pp, vv.x, acc2[2*i  ]);
                acc2[2*i+1] = f2fma(pp, vv.y, acc2[2*i+1]);
            }
        }
    }
    float* op = g_pacc[kt] + (size_t)row * HD;
    #pragma unroll
    for (int i = 0; i < 8; i++) {
        float x0, x1, x2, x3;
        upk(acc2[2*i], x0, x1); upk(acc2[2*i+1], x2, x3);
        float4 o; o.x = x0; o.y = x1; o.z = x2; o.w = x3;
        *(float4*)(op + 4*i) = o;
    }
    g_pl[kt][row] = l;
}

// -------- merge split-K partials into g_att layout --------
__global__ void k_merge() {
    int idx = blockIdx.x * 256 + threadIdx.x;          // < NROWS*HD
    int row = idx >> 5;
    int c = idx & 31;
    int bh = row / NSEQ, n = row % NSEQ;
    int h = bh & 7, b = bh >> 3;
    float a = g_pacc[0][idx] + g_pacc[1][idx];
    float l = g_pl[0][row] + g_pl[1][row];
    g_att[(size_t)(b * NSEQ + n) * DIMC + h * HD + c] = a / l;
}

#define FLASH_SMEM ((TAB_PAD + 2048) * 4 + MTILE * FT * 4)

extern "C" void kernel_launch(void* const* d_in, const int* in_sizes, int n_in,
                              void* d_out, int out_size) {
    const float*     x     = (const float*)d_in[0];
    const long long* rpi   = (const long long*)d_in[1];
    const float*     rct   = (const float*)d_in[2];
    const float*     seq   = (const float*)d_in[3];
    const float*     Wqkv  = (const float*)d_in[5];
    const float*     bqkv  = (const float*)d_in[6];
    const float*     temp  = (const float*)d_in[7];
    const float*     emb   = (const float*)d_in[8];
    const float*     Wproj = (const float*)d_in[9];
    const float*     bproj = (const float*)d_in[10];
    const float*     W1    = (const float*)d_in[11];
    const float*     b1    = (const float*)d_in[12];
    const float*     W2    = (const float*)d_in[13];
    const float*     b2    = (const float*)d_in[14];
    float* out = (float*)d_out;

    float *p_qkv, *p_att;
    cudaGetSymbolAddress((void**)&p_qkv, g_qkv);
    cudaGetSymbolAddress((void**)&p_att, g_att);

    static int smem_set = 0;
    if (!smem_set) {
        cudaFuncSetAttribute(k_flash, cudaFuncAttributeMaxDynamicSharedMemorySize,
                             FLASH_SMEM);
        smem_set = 1;
    }

    k_flag_init<<<1, 1>>>();
    k_flag_scan<<<128, 256>>>(rpi);
    k_idx_convert<<<dim3(NSEQ/32, NSEQ/32), dim3(32, 8)>>>(rpi);
    k_cpb<<<(NTAB + 255) / 256, 256>>>(rct, W1, b1, W2, b2);
    k_maxb<<<1, dim3(32, 8)>>>();
    k_gemm<<<dim3(3 * DIMC / BN, MROWS / BM), 256>>>(x, Wqkv, bqkv, p_qkv,
                                                     MROWS, 3 * DIMC, DIMC);
    k_qkvpost<<<(NB * NH * NSEQ) / 4, 128>>>(temp, seq, emb);
    k_flash<<<dim3(NB * NH, NSEQ / FT, 2), FT, FLASH_SMEM>>>();
    k_merge<<<(NROWS * HD) / 256, 256>>>();
    k_gemm<<<dim3(DIMC / BN, MROWS / BM), 256>>>(p_att, Wproj, bproj, out,
                                                 MROWS, DIMC, DIMC);
}

// round 5
// speedup vs baseline: 1.4929x; 1.4929x over previous
#include <cuda_runtime.h>

#define NB 2
#define NSEQ 2304
#define NH 8
#define HD 32
#define DIMC 256
#define NTAB 9025
#define CPBH 512
#define MROWS (NB*NSEQ)          // 4608
#define NROWS (NB*NH*NSEQ)       // 36864

typedef unsigned long long u64;
typedef unsigned short u16;

// ---- packed f32x2 helpers (Blackwell FFMA2 — PTX only) ----
__device__ __forceinline__ u64 pk(float lo, float hi) {
    u64 r; asm("mov.b64 %0,{%1,%2};" : "=l"(r) : "f"(lo), "f"(hi)); return r;
}
__device__ __forceinline__ void upk(u64 v, float& lo, float& hi) {
    asm("mov.b64 {%0,%1},%2;" : "=f"(lo), "=f"(hi) : "l"(v));
}
__device__ __forceinline__ u64 f2fma(u64 a, u64 b, u64 c) {
    u64 r; asm("fma.rn.f32x2 %0,%1,%2,%3;" : "=l"(r) : "l"(a), "l"(b), "l"(c)); return r;
}
__device__ __forceinline__ u64 f2mul(u64 a, u64 b) {
    u64 r; asm("mul.rn.f32x2 %0,%1,%2;" : "=l"(r) : "l"(a), "l"(b)); return r;
}
__device__ __forceinline__ u64 f2add(u64 a, u64 b) {
    u64 r; asm("add.rn.f32x2 %0,%1,%2;" : "=l"(r) : "l"(a), "l"(b)); return r;
}

// ---- cp.async helpers ----
__device__ __forceinline__ void cpa16(unsigned smem, const void* g) {
    asm volatile("cp.async.cg.shared.global [%0], [%1], 16;" :: "r"(smem), "l"(g));
}
__device__ __forceinline__ void cpa_commit() {
    asm volatile("cp.async.commit_group;" ::: "memory");
}
__device__ __forceinline__ void cpa_wait1() {
    asm volatile("cp.async.wait_group 1;" ::: "memory");
}

// -------- device scratch --------
__device__ float g_qkv[MROWS*3*DIMC];
__device__ float g_q[NROWS*HD];
__device__ float g_k[NROWS*HD];
__device__ float g_v[NROWS*HD];
__device__ float g_att[MROWS*DIMC];
__device__ float g_tab[NH*NTAB];
__device__ u16   g_idxT[NSEQ*NSEQ];         // TRANSPOSED: [m][n], fits u16 (NTAB<65536)
__device__ int   g_is64;

// -------- dtype probe --------
__global__ void k_flag_init() { g_is64 = 1; }

__global__ void k_flag_scan(const long long* __restrict__ p) {
    const long total = 2000000;
    for (long i = (long)blockIdx.x * blockDim.x + threadIdx.x; i < total;
         i += (long)gridDim.x * blockDim.x) {
        long long v = p[i];
        if (v < 0 || v >= NTAB) g_is64 = 0;
    }
}

// -------- convert int64->u16 AND transpose (tiled) --------
__global__ void k_idx_convert(const long long* __restrict__ p) {
    __shared__ int t[32][33];
    int is64 = g_is64;
    const int* p32 = (const int*)p;
    int bx = blockIdx.x * 32, by = blockIdx.y * 32;
    #pragma unroll
    for (int j = 0; j < 32; j += 8) {
        long src = (long)(by + threadIdx.y + j) * NSEQ + bx + threadIdx.x;
        t[threadIdx.y + j][threadIdx.x] = is64 ? (int)p[src] : p32[src];
    }
    __syncthreads();
    #pragma unroll
    for (int j = 0; j < 32; j += 8) {
        long dst = (long)(bx + threadIdx.y + j) * NSEQ + by + threadIdx.x;
        g_idxT[dst] = (u16)t[threadIdx.x][threadIdx.y + j];
    }
}

// -------- CPB MLP --------
__global__ void k_cpb(const float* __restrict__ tbl, const float* __restrict__ W1,
                      const float* __restrict__ b1, const float* __restrict__ W2,
                      const float* __restrict__ b2) {
    int w = blockIdx.x * 4 + (threadIdx.x >> 5);
    int lane = threadIdx.x & 31;
    if (w >= NTAB) return;
    float c0 = tbl[2*w], c1 = tbl[2*w+1];
    u64 a01 = 0, a23 = 0, a45 = 0, a67 = 0;
    for (int j = lane; j < CPBH; j += 32) {
        float hd = fmaxf(fmaf(c0, W1[2*j], fmaf(c1, W1[2*j+1], b1[j])), 0.f);
        u64 hh = pk(hd, hd);
        a01 = f2fma(hh, pk(W2[0*CPBH+j], W2[1*CPBH+j]), a01);
        a23 = f2fma(hh, pk(W2[2*CPBH+j], W2[3*CPBH+j]), a23);
        a45 = f2fma(hh, pk(W2[4*CPBH+j], W2[5*CPBH+j]), a45);
        a67 = f2fma(hh, pk(W2[6*CPBH+j], W2[7*CPBH+j]), a67);
    }
    float a[8];
    upk(a01, a[0], a[1]); upk(a23, a[2], a[3]);
    upk(a45, a[4], a[5]); upk(a67, a[6], a[7]);
    #pragma unroll
    for (int i = 0; i < 8; i++)
        #pragma unroll
        for (int off = 16; off; off >>= 1)
            a[i] += __shfl_xor_sync(0xffffffffu, a[i], off);
    if (lane == 0) {
        #pragma unroll
        for (int i = 0; i < 8; i++) g_tab[i*NTAB + w] = a[i] + b2[i];
    }
}

// -------- tiled fp32 GEMM with packed FFMA2: C = A @ W^T + bias --------
#define BM 128
#define BN 64
#define BK 16
__global__ void __launch_bounds__(256) k_gemm(
        const float* __restrict__ A, const float* __restrict__ W,
        const float* __restrict__ bias, float* __restrict__ C,
        int M, int N, int K) {
    __shared__ __align__(16) float As[BK][BM];
    __shared__ __align__(16) float Bs[BK][BN];
    int tid = threadIdx.x;
    int row0 = blockIdx.y * BM, col0 = blockIdx.x * BN;
    int ty = tid >> 4, tx = tid & 15;
    u64 acc2[4][4];
    #pragma unroll
    for (int i = 0; i < 4; i++)
        #pragma unroll
        for (int j = 0; j < 4; j++) acc2[i][j] = 0ull;

    for (int k0 = 0; k0 < K; k0 += BK) {
        #pragma unroll
        for (int jj = 0; jj < 2; jj++) {
            int f = tid + jj * 256;
            int ar = f >> 2, ac = (f & 3) << 2;
            float4 v = *(const float4*)(A + (size_t)(row0 + ar) * K + k0 + ac);
            As[ac  ][ar] = v.x; As[ac+1][ar] = v.y;
            As[ac+2][ar] = v.z; As[ac+3][ar] = v.w;
        }
        {
            int f = tid;
            int br = f >> 2, bc = (f & 3) << 2;
            float4 v = *(const float4*)(W + (size_t)(col0 + br) * K + k0 + bc);
            Bs[bc  ][br] = v.x; Bs[bc+1][br] = v.y;
            Bs[bc+2][br] = v.z; Bs[bc+3][br] = v.w;
        }
        __syncthreads();
        #pragma unroll
        for (int kk = 0; kk < BK; kk++) {
            ulonglong2 aA = *(const ulonglong2*)&As[kk][ty*8];
            ulonglong2 aB = *(const ulonglong2*)&As[kk][ty*8 + 4];
            u64 a2[4] = {aA.x, aA.y, aB.x, aB.y};
            float4 bq = *(const float4*)&Bs[kk][tx*4];
            u64 bd[4] = {pk(bq.x,bq.x), pk(bq.y,bq.y), pk(bq.z,bq.z), pk(bq.w,bq.w)};
            #pragma unroll
            for (int i = 0; i < 4; i++)
                #pragma unroll
                for (int j = 0; j < 4; j++)
                    acc2[i][j] = f2fma(a2[i], bd[j], acc2[i][j]);
        }
        __syncthreads();
    }
    float4 bb = *(const float4*)(bias + col0 + tx*4);
    #pragma unroll
    for (int i = 0; i < 4; i++) {
        float lo[4], hi[4];
        #pragma unroll
        for (int j = 0; j < 4; j++) upk(acc2[i][j], lo[j], hi[j]);
        float4 o0, o1;
        o0.x = lo[0]+bb.x; o0.y = lo[1]+bb.y; o0.z = lo[2]+bb.z; o0.w = lo[3]+bb.w;
        o1.x = hi[0]+bb.x; o1.y = hi[1]+bb.y; o1.z = hi[2]+bb.z; o1.w = hi[3]+bb.w;
        *(float4*)(C + (size_t)(row0 + ty*8 + 2*i    ) * N + col0 + tx*4) = o0;
        *(float4*)(C + (size_t)(row0 + ty*8 + 2*i + 1) * N + col0 + tx*4) = o1;
    }
}

// -------- qkv postprocess --------
__global__ void k_qkvpost(const float* __restrict__ temp, const float* __restrict__ seq,
                          const float* __restrict__ emb) {
    int gid = blockIdx.x * 4 + (threadIdx.x >> 5);
    int lane = threadIdx.x & 31;
    int n  = gid % NSEQ;
    int bh = gid / NSEQ;
    int h = bh & 7, b = bh >> 3;
    const float* rp = g_qkv + (size_t)(b * NSEQ + n) * (3 * DIMC);
    float qv = rp[            h * HD + lane];
    float kv = rp[DIMC      + h * HD + lane];
    float vv = rp[2 * DIMC  + h * HD + lane];
    float sq = qv * qv, sk = kv * kv;
    #pragma unroll
    for (int off = 16; off; off >>= 1) {
        sq += __shfl_xor_sync(0xffffffffu, sq, off);
        sk += __shfl_xor_sync(0xffffffffu, sk, off);
    }
    sq = sqrtf(sq); sk = sqrtf(sk);
    float scale = log1pf(expf(temp[h])) * seq[0];
    float qn = (qv / fmaxf(sq, 1e-12f) + emb[h * HD + lane]) * scale;
    float kn =  kv / fmaxf(sk, 1e-12f);
    size_t o = (size_t)gid * HD + lane;
    g_q[o] = qn; g_k[o] = kn; g_v[o] = vv;
}

// -------- flash attention: online softmax + cp.async double-buffered tiles --------
#define FT 256
#define MTILE 32
#define NT (NSEQ/MTILE)                               // 72
#define TAB_PAD 9056
// smem float offsets
#define OFF_K   TAB_PAD                               // K[2][1024] floats
#define OFF_V   (TAB_PAD + 2048)                      // V[2][1024] floats
#define OFF_I   (TAB_PAD + 4096)                      // idx[2][4096] u16 (2 bufs x 8192 u16)
#define FLASH_FLOATS (TAB_PAD + 4096 + 8192)
#define FLASH_SMEM (FLASH_FLOATS * 4)

__global__ void __launch_bounds__(FT) k_flash() {
    extern __shared__ __align__(16) float dsm[];
    float* tab_s = dsm;

    int tid = threadIdx.x;
    int bh = blockIdx.x;
    int h = bh & 7, b = bh >> 3;
    int n0 = blockIdx.y * FT;
    int n = n0 + tid;

    unsigned smem_base = (unsigned)__cvta_generic_to_shared(dsm);

    const float* kb = g_k + (size_t)bh * NSEQ * HD;
    const float* vb = g_v + (size_t)bh * NSEQ * HD;

    // prefetch issue for tile t into buffer (t&1); clamped so always in-bounds
    auto prefetch = [&](int t) {
        int tt = t < NT ? t : NT - 1;
        int buf = t & 1;
        int m0 = tt * MTILE;
        // K tile: 4KB, 16B per thread
        cpa16(smem_base + (OFF_K + buf * 1024) * 4 + tid * 16,
              kb + (size_t)m0 * HD + tid * 4);
        // V tile
        cpa16(smem_base + (OFF_V + buf * 1024) * 4 + tid * 16,
              vb + (size_t)m0 * HD + tid * 4);
        // idx tile: 32 rows x 256 u16 = 16KB = 1024 chunks of 16B, 4 per thread
        #pragma unroll
        for (int c = 0; c < 4; c++) {
            int id = c * FT + tid;              // 0..1023
            int r = id >> 5;                    // 32 chunks of 16B per row
            int c8 = (id & 31) << 3;            // u16 offset within row
            cpa16(smem_base + (OFF_I + buf * 4096) * 4 + id * 16,
                  g_idxT + (size_t)(m0 + r) * NSEQ + n0 + c8);
        }
        cpa_commit();
    };

    prefetch(0);
    prefetch(1);

    // load bias table while cp.asyncs fly
    for (int i = tid; i < NTAB; i += FT) tab_s[i] = g_tab[h * NTAB + i];

    u64 q2[16];
    const ulonglong2* qp = (const ulonglong2*)(g_q + ((size_t)bh * NSEQ + n) * HD);
    #pragma unroll
    for (int i = 0; i < 8; i++) { ulonglong2 t = qp[i]; q2[2*i] = t.x; q2[2*i+1] = t.y; }

    u64 acc2[16];
    #pragma unroll
    for (int i = 0; i < 16; i++) acc2[i] = 0ull;
    float l = 0.f, mx = -1e30f;

    for (int t = 0; t < NT; t++) {
        int buf = t & 1;
        cpa_wait1();                                   // tile t landed
        __syncthreads();                               // also covers tab_s on t==0
        const float* Ks = dsm + OFF_K + buf * 1024;
        const float* Vs = dsm + OFF_V + buf * 1024;
        const u16*   Is = (const u16*)(dsm + OFF_I + buf * 4096);
        #pragma unroll 2
        for (int m = 0; m < MTILE; m++) {
            float bias = tab_s[(int)Is[m * FT + tid]];
            const ulonglong2* kr = (const ulonglong2*)(Ks + m * HD);
            u64 s0 = pk(bias, 0.f), s1 = 0ull, s2 = 0ull, s3 = 0ull;
            #pragma unroll
            for (int i = 0; i < 4; i++) {
                ulonglong2 ka = kr[2*i], kbb = kr[2*i+1];
                s0 = f2fma(q2[4*i  ], ka.x,  s0);
                s1 = f2fma(q2[4*i+1], ka.y,  s1);
                s2 = f2fma(q2[4*i+2], kbb.x, s2);
                s3 = f2fma(q2[4*i+3], kbb.y, s3);
            }
            u64 st = f2add(f2add(s0, s1), f2add(s2, s3));
            float slo, shi; upk(st, slo, shi);
            float s = slo + shi;
            if (__any_sync(0xffffffffu, s > mx)) {     // rare after warmup
                float nm = fmaxf(mx, s);
                float c = __expf(mx - nm);
                l *= c;
                u64 cc = pk(c, c);
                #pragma unroll
                for (int i = 0; i < 16; i++) acc2[i] = f2mul(acc2[i], cc);
                mx = nm;
            }
            float p = __expf(s - mx);
            l += p;
            u64 pp = pk(p, p);
            const ulonglong2* vr = (const ulonglong2*)(Vs + m * HD);
            #pragma unroll
            for (int i = 0; i < 8; i++) {
                ulonglong2 vv = vr[i];
                acc2[2*i  ] = f2fma(pp, vv.x, acc2[2*i  ]);
                acc2[2*i+1] = f2fma(pp, vv.y, acc2[2*i+1]);
            }
        }
        __syncthreads();                               // done reading buf
        prefetch(t + 2);                               // refill this buffer
    }

    float inv = 1.f / l;
    float* op = g_att + (size_t)(b * NSEQ + n) * DIMC + h * HD;
    #pragma unroll
    for (int i = 0; i < 8; i++) {
        float x0, x1, x2, x3;
        upk(acc2[2*i], x0, x1); upk(acc2[2*i+1], x2, x3);
        float4 o; o.x = x0*inv; o.y = x1*inv; o.z = x2*inv; o.w = x3*inv;
        *(float4*)(op + 4*i) = o;
    }
}

extern "C" void kernel_launch(void* const* d_in, const int* in_sizes, int n_in,
                              void* d_out, int out_size) {
    const float*     x     = (const float*)d_in[0];
    const long long* rpi   = (const long long*)d_in[1];
    const float*     rct   = (const float*)d_in[2];
    const float*     seq   = (const float*)d_in[3];
    const float*     Wqkv  = (const float*)d_in[5];
    const float*     bqkv  = (const float*)d_in[6];
    const float*     temp  = (const float*)d_in[7];
    const float*     emb   = (const float*)d_in[8];
    const float*     Wproj = (const float*)d_in[9];
    const float*     bproj = (const float*)d_in[10];
    const float*     W1    = (const float*)d_in[11];
    const float*     b1    = (const float*)d_in[12];
    const float*     W2    = (const float*)d_in[13];
    const float*     b2    = (const float*)d_in[14];
    float* out = (float*)d_out;

    float *p_qkv, *p_att;
    cudaGetSymbolAddress((void**)&p_qkv, g_qkv);
    cudaGetSymbolAddress((void**)&p_att, g_att);

    cudaFuncSetAttribute(k_flash, cudaFuncAttributeMaxDynamicSharedMemorySize,
                         FLASH_SMEM);

    k_flag_init<<<1, 1>>>();
    k_flag_scan<<<128, 256>>>(rpi);
    k_idx_convert<<<dim3(NSEQ/32, NSEQ/32), dim3(32, 8)>>>(rpi);
    k_cpb<<<(NTAB + 3) / 4, 128>>>(rct, W1, b1, W2, b2);
    k_gemm<<<dim3(3 * DIMC / BN, MROWS / BM), 256>>>(x, Wqkv, bqkv, p_qkv,
                                                     MROWS, 3 * DIMC, DIMC);
    k_qkvpost<<<(NB * NH * NSEQ) / 4, 128>>>(temp, seq, emb);
    k_flash<<<dim3(NB * NH, NSEQ / FT), FT, FLASH_SMEM>>>();
    k_gemm<<<dim3(DIMC / BN, MROWS / BM), 256>>>(p_att, Wproj, bproj, out,
                                                 MROWS, DIMC, DIMC);
}